// round 17
// baseline (speedup 1.0000x reference)
#include <cuda_runtime.h>
#include <cuda_bf16.h>
#include <math_constants.h>
#include <cstdint>

#define BATCH 8192
#define DIM   512
#define NCLS  512
#define T_INV 14.2857142857142857f  // 1/0.07

#define NSTRIP 64                  // 64 strips of 128 rows
#define NTILE  (NSTRIP * (NSTRIP + 1) / 2)   // 2080 upper-tri tiles
#define NSLOT  64
#define PSTRIDE 8                  // floats per partial record (5 used)
#define MAXM   96                  // class-size cap (P(exceed) ~ 1e-50 at mean 16)

#define MT     128
#define NT     128
#define KC     64                  // bf16 halves per chunk
#define NCHUNK (DIM / KC)          // 8
#define NSTAGE 3
#define THREADS 512

#define PITCHH 72                  // halves per SMEM row (144B; conflict-free frags)
#define AB_HALVES (MT * PITCHH)            // 9216 halves per operand
#define STAGE_HALVES (2 * AB_HALVES)
#define STAGE_BYTES  (STAGE_HALVES * 2)    // 36864
#define CPITCH 132
#define PS_OFF  (128 * CPITCH)             // floats; PsR/PsC after C tile
#define SMEM_BYTES (NSTAGE * STAGE_BYTES)  // 110592
#define GRAM_SMEM (MAXM * DIM * 4)         // 196608

// ---------------- static scratch ----------------
__device__ float  g_f[BATCH * DIM];        // normalized fp32 features
__device__ __nv_bfloat16 g_fb[BATCH * DIM];
__device__ int   g_idx[BATCH];
__device__ unsigned g_Gkey;
__device__ float g_part[(size_t)BATCH * NSLOT * PSTRIDE];
__device__ int   g_ccount[NCLS], g_coff[NCLS];
__device__ int   g_bmem[BATCH];
__device__ float g_D1[BATCH], g_H[BATCH], g_B[BATCH], g_posn[BATCH];

// ---------------- helpers ----------------
__device__ __forceinline__ uint32_t smem_u32(const void* p) {
    uint32_t a;
    asm("{ .reg .u64 t; cvta.to.shared.u64 t, %1; cvt.u32.u64 %0, t; }" : "=r"(a) : "l"(p));
    return a;
}
__device__ __forceinline__ void cpa16(uint32_t dst, const void* src) {
    asm volatile("cp.async.cg.shared.global [%0], [%1], 16;" :: "r"(dst), "l"(src));
}
#define CP_COMMIT() asm volatile("cp.async.commit_group;" ::: "memory")
#define CP_WAIT1()  asm volatile("cp.async.wait_group 1;" ::: "memory")
#define CP_WAIT0()  asm volatile("cp.async.wait_group 0;" ::: "memory")

__device__ __forceinline__ void ldsm_x4(uint32_t* r, uint32_t addr) {
    asm volatile("ldmatrix.sync.aligned.m8n8.x4.shared.b16 {%0,%1,%2,%3}, [%4];"
                 : "=r"(r[0]), "=r"(r[1]), "=r"(r[2]), "=r"(r[3]) : "r"(addr));
}
__device__ __forceinline__ void mma16(float* c, const uint32_t* a, uint32_t b0, uint32_t b1) {
    asm volatile(
        "mma.sync.aligned.m16n8k16.row.col.f32.bf16.bf16.f32 "
        "{%0,%1,%2,%3}, {%4,%5,%6,%7}, {%8,%9}, {%0,%1,%2,%3};"
        : "+f"(c[0]), "+f"(c[1]), "+f"(c[2]), "+f"(c[3])
        : "r"(a[0]), "r"(a[1]), "r"(a[2]), "r"(a[3]), "r"(b0), "r"(b1));
}

__device__ __forceinline__ unsigned fkey(float f) {
    unsigned u = __float_as_uint(f);
    return (u & 0x80000000u) ? ~u : (u | 0x80000000u);
}
__device__ __forceinline__ float funkey(unsigned k) {
    unsigned u = (k & 0x80000000u) ? (k & 0x7FFFFFFFu) : ~k;
    return __uint_as_float(u);
}
__device__ __forceinline__ void top5_ins(float v, float& t0, float& t1, float& t2,
                                         float& t3, float& t4) {
    if (v > t4) {
        float w = v, tmp;
        if (w > t0) { tmp = t0; t0 = w; w = tmp; }
        if (w > t1) { tmp = t1; t1 = w; w = tmp; }
        if (w > t2) { tmp = t2; t2 = w; w = tmp; }
        if (w > t3) { tmp = t3; t3 = w; w = tmp; }
        t4 = w;
    }
}

// ---------------------------------------------------------------------------
// Kernel 0: dtype-agnostic index canonicalization (int32 vs int64) + G reset
// ---------------------------------------------------------------------------
__global__ void prep_idx_kernel(const int* __restrict__ raw) {
    __shared__ int sh[256];
    int tid = threadIdx.x;
    int acc = 0;
    for (int i = tid; i < BATCH / 2; i += 256) acc |= raw[2 * i + 1];
    sh[tid] = acc;
    __syncthreads();
    for (int s = 128; s; s >>= 1) { if (tid < s) sh[tid] |= sh[tid + s]; __syncthreads(); }
    bool is64 = (sh[0] == 0);
    for (int i = tid; i < BATCH; i += 256) g_idx[i] = is64 ? raw[2 * i] : raw[i];
    if (tid == 0) g_Gkey = 0u;
}

// ---------------------------------------------------------------------------
// Kernel 1: L2 normalize -> fp32 g_f + bf16 g_fb
// ---------------------------------------------------------------------------
__global__ void normalize_kernel(const float* __restrict__ x) {
    int row = blockIdx.x;
    int t = threadIdx.x;
    float4 v = ((const float4*)(x + row * DIM))[t];
    float ss = v.x * v.x + v.y * v.y + v.z * v.z + v.w * v.w;
    #pragma unroll
    for (int o = 16; o; o >>= 1) ss += __shfl_xor_sync(0xffffffffu, ss, o);
    __shared__ float ws[4];
    if ((t & 31) == 0) ws[t >> 5] = ss;
    __syncthreads();
    float inv = 1.0f / fmaxf(sqrtf(ws[0] + ws[1] + ws[2] + ws[3]), 1e-12f);
    float4 f = make_float4(v.x * inv, v.y * inv, v.z * inv, v.w * inv);
    ((float4*)(g_f + (size_t)row * DIM))[t] = f;
    __nv_bfloat162 p0 = __floats2bfloat162_rn(f.x, f.y);
    __nv_bfloat162 p1 = __floats2bfloat162_rn(f.z, f.w);
    uint2 w;
    w.x = *(uint32_t*)&p0;
    w.y = *(uint32_t*)&p1;
    ((uint2*)(g_fb + row * DIM))[t] = w;
}

// dummy launch to keep ncu's capture slot on sim_kernel
__global__ void dummy_kernel() {}

// ---------------------------------------------------------------------------
// Kernels: class buckets (count, prefix, fill) — validated in R11
// ---------------------------------------------------------------------------
__global__ void class_count_kernel() {
    int c = blockIdx.x, lane = threadIdx.x;
    int cnt = 0;
    for (int b = lane; b < BATCH; b += 32) cnt += (g_idx[b] == c);
    #pragma unroll
    for (int o = 16; o; o >>= 1) cnt += __shfl_xor_sync(0xffffffffu, cnt, o);
    if (lane == 0) g_ccount[c] = cnt;
}
__global__ void class_prefix_kernel() {
    __shared__ int sh[NCLS];
    int t = threadIdx.x;
    int mine = g_ccount[t];
    sh[t] = mine;
    __syncthreads();
    for (int o = 1; o < NCLS; o <<= 1) {
        int u = (t >= o) ? sh[t - o] : 0;
        __syncthreads();
        sh[t] += u;
        __syncthreads();
    }
    g_coff[t] = sh[t] - mine;   // exclusive prefix
}
__global__ void class_fill_kernel() {
    int c = blockIdx.x, lane = threadIdx.x;
    int off = g_coff[c];
    int cnt = 0;
    for (int base = 0; base < BATCH; base += 32) {
        int j = base + lane;
        bool m = (g_idx[j] == c);
        unsigned mask = __ballot_sync(0xffffffffu, m);
        if (m) g_bmem[off + cnt + __popc(mask & ((1u << lane) - 1))] = j;
        cnt += __popc(mask);
    }
}

// ---------------------------------------------------------------------------
// Kernel: per-class Gram — exact fp32 positive stats (D1, B, n) per row
// ---------------------------------------------------------------------------
__global__ __launch_bounds__(256, 1)
void gram_kernel() {
    extern __shared__ float gs[];            // MAXM x 512 member rows
    __shared__ int mlist[MAXM];
    const int c = blockIdx.x, tid = threadIdx.x;
    int cnt = g_ccount[c];
    if (cnt > MAXM) cnt = MAXM;
    const int off = g_coff[c];
    for (int m = tid; m < cnt; m += 256) mlist[m] = g_bmem[off + m];
    __syncthreads();
    for (int i = tid; i < cnt * 128; i += 256) {
        int m = i >> 7, q = i & 127;
        ((float4*)(gs + m * DIM))[q] = ((const float4*)(g_f + (size_t)mlist[m] * DIM))[q];
    }
    __syncthreads();

    const int lane = tid & 31, w = tid >> 5;
    for (int i = w; i < cnt; i += 8) {
        const float* fi = gs + i * DIM;
        float S = 0.f, P = 0.f, rm = -CUDART_INF_F;
        for (int j = 0; j < cnt; j++) {
            if (j == i) continue;
            const float* fj = gs + j * DIM;
            float s = 0.f;
            #pragma unroll
            for (int k = 0; k < 16; k++)
                s += fi[lane + 32 * k] * fj[lane + 32 * k];
            #pragma unroll
            for (int o = 16; o; o >>= 1) s += __shfl_xor_sync(0xffffffffu, s, o);
            S += s; rm = fmaxf(rm, s); P += __expf(s * T_INV);
        }
        if (lane == 0) {
            int r = mlist[i];
            if (cnt > 1) {
                g_D1[r] = __expf(-rm * T_INV) * P;
                g_B[r]  = (S * T_INV) / (float)(cnt - 1);
                g_posn[r] = (float)(cnt - 1);
            } else {
                g_D1[r] = 0.f; g_B[r] = 0.f; g_posn[r] = 0.f;
            }
        }
    }
}

// ---------------------------------------------------------------------------
// Kernel 2: symmetric-triangle HMMA bf16 GEMM, 512 threads, 3-stage ring,
//   top-5-only dual scans (no positive logic)
// ---------------------------------------------------------------------------
__global__ __launch_bounds__(THREADS, 2)
void sim_kernel() {
    extern __shared__ float smem[];
    const uint32_t s_base = smem_u32(smem);
    const int tid  = threadIdx.x;
    const int lane = tid & 31, warp = tid >> 5;

    // decode blockIdx -> (I, J) with I <= J
    const int b = blockIdx.x;
    int J = (int)((sqrtf(8.0f * b + 1.0f) - 1.0f) * 0.5f);
    while ((J + 1) * (J + 2) / 2 <= b) ++J;
    while (J * (J + 1) / 2 > b) --J;
    const int I = b - J * (J + 1) / 2;
    const int row0 = I * MT;
    const int col0 = J * NT;
    const bool DIAG = (I == J);

    // persistent prefetch pointers: 4 cp.async per thread per chunk
    const int pr = tid >> 3, sg8 = (tid & 7) * 8;
    const __nv_bfloat16* srcA0 = g_fb + (size_t)(row0 + pr) * DIM + sg8;
    const __nv_bfloat16* srcA1 = srcA0 + (size_t)64 * DIM;
    const __nv_bfloat16* srcB0 = g_fb + (size_t)(col0 + pr) * DIM + sg8;
    const __nv_bfloat16* srcB1 = srcB0 + (size_t)64 * DIM;
    const uint32_t dA0 = (uint32_t)((pr * PITCHH + sg8) * 2);
    const uint32_t dA1 = (uint32_t)(((pr + 64) * PITCHH + sg8) * 2);
    const uint32_t dB0 = AB_HALVES * 2 + dA0;
    const uint32_t dB1 = AB_HALVES * 2 + dA1;

    #define PREFETCH(stb_) do {                 \
        cpa16((stb_) + dA0, srcA0);             \
        cpa16((stb_) + dA1, srcA1);             \
        cpa16((stb_) + dB0, srcB0);             \
        cpa16((stb_) + dB1, srcB1);             \
        CP_COMMIT();                            \
        srcA0 += KC; srcA1 += KC;               \
        srcB0 += KC; srcB1 += KC;               \
    } while (0)

    const int wm = warp >> 2, wn = warp & 3;   // 4x4 warp grid, 32x32 tiles
    const int qg = lane >> 2, qt = lane & 3;

    uint32_t aoff[2], boff[2];
    {
        const int l7 = lane & 7, l8 = (lane >> 3) & 1, l16 = (lane >> 4) & 1;
        #pragma unroll
        for (int i = 0; i < 2; i++) {
            int rowA = wm * 32 + i * 16 + l8 * 8 + l7;
            aoff[i] = (uint32_t)((rowA * PITCHH + l16 * 8) * 2);
        }
        #pragma unroll
        for (int jp = 0; jp < 2; jp++) {
            int nB = wn * 32 + jp * 16 + l16 * 8 + l7;
            boff[jp] = (uint32_t)(AB_HALVES * 2 + (nB * PITCHH + l8 * 8) * 2);
        }
    }

    float acc[2][4][4];
    #pragma unroll
    for (int i = 0; i < 2; i++)
        #pragma unroll
        for (int j = 0; j < 4; j++)
            #pragma unroll
            for (int q = 0; q < 4; q++) acc[i][j][q] = 0.f;

    PREFETCH(s_base);
    PREFETCH(s_base + STAGE_BYTES);

    for (int c = 0; c < NCHUNK; c++) {
        const int st = c % NSTAGE;
        if (c < NCHUNK - 1) { CP_WAIT1(); } else { CP_WAIT0(); }
        __syncthreads();   // stage st ready; stage (c+2)%3 fully consumed

        const uint32_t stb = s_base + st * STAGE_BYTES;
        #pragma unroll
        for (int ks = 0; ks < 4; ks++) {
            const uint32_t ko = ks * 32;
            uint32_t a0[4], a1[4], bb[2][4];
            ldsm_x4(a0, stb + aoff[0] + ko);
            ldsm_x4(a1, stb + aoff[1] + ko);
            ldsm_x4(bb[0], stb + boff[0] + ko);
            ldsm_x4(bb[1], stb + boff[1] + ko);
            #pragma unroll
            for (int jp = 0; jp < 2; jp++) {
                mma16(acc[0][2 * jp],     a0, bb[jp][0], bb[jp][1]);
                mma16(acc[1][2 * jp],     a1, bb[jp][0], bb[jp][1]);
                mma16(acc[0][2 * jp + 1], a0, bb[jp][2], bb[jp][3]);
                mma16(acc[1][2 * jp + 1], a1, bb[jp][2], bb[jp][3]);
            }
            if (ks == 0 && c + 2 < NCHUNK)
                PREFETCH(s_base + ((c + 2) % NSTAGE) * STAGE_BYTES);
        }
    }
    __syncthreads();   // all mma ldsm reads done before C tile overwrites stages
    #undef PREFETCH

    // stage C tile (aliases stage buffers) — float2 stores
    float* Cs = smem;
    float* PsR = smem + PS_OFF;           // 512 x 5 row partials
    float* PsC = PsR + THREADS * 5;       // 512 x 5 col partials
    #pragma unroll
    for (int i = 0; i < 2; i++) {
        #pragma unroll
        for (int j = 0; j < 4; j++) {
            int r = wm * 32 + i * 16 + qg;
            int cc = wn * 32 + j * 8 + 2 * qt;
            *(float2*)(Cs + r * CPITCH + cc)       = make_float2(acc[i][j][0], acc[i][j][1]);
            *(float2*)(Cs + (r + 8) * CPITCH + cc) = make_float2(acc[i][j][2], acc[i][j][3]);
        }
    }
    __syncthreads();

    const int sidx = tid & 127, squad = tid >> 7;   // 4 quads per row/col

    // ---- row scan: top-5 of strip I rows over strip J cols (32 cols each) ----
    {
        const int myrow = row0 + sidx;
        float t0 = -CUDART_INF_F, t1 = -CUDART_INF_F, t2 = -CUDART_INF_F,
              t3 = -CUDART_INF_F, t4 = -CUDART_INF_F;
        const float4* crow4 = (const float4*)(Cs + sidx * CPITCH) + squad * 8;
        const int cbase0 = col0 + squad * 32;
        #pragma unroll 8
        for (int p = 0; p < 8; p++) {
            float4 v = crow4[p];
            float m = fmaxf(fmaxf(v.x, v.y), fmaxf(v.z, v.w));
            if (m > t4) {
                int cb = cbase0 + p * 4;
                if (!DIAG || cb + 0 != myrow) top5_ins(v.x, t0, t1, t2, t3, t4);
                if (!DIAG || cb + 1 != myrow) top5_ins(v.y, t0, t1, t2, t3, t4);
                if (!DIAG || cb + 2 != myrow) top5_ins(v.z, t0, t1, t2, t3, t4);
                if (!DIAG || cb + 3 != myrow) top5_ins(v.w, t0, t1, t2, t3, t4);
            }
        }
        float* pp = PsR + (sidx * 4 + squad) * 5;
        pp[0] = t0; pp[1] = t1; pp[2] = t2; pp[3] = t3; pp[4] = t4;
    }

    // ---- col scan: top-5 of strip J rows over strip I cols (32 rows each) ----
    if (!DIAG) {
        float t0 = -CUDART_INF_F, t1 = -CUDART_INF_F, t2 = -CUDART_INF_F,
              t3 = -CUDART_INF_F, t4 = -CUDART_INF_F;
        const int rbase = squad * 32;
        #pragma unroll 8
        for (int p = 0; p < 8; p++) {
            int rr = rbase + p * 4;
            float v0 = Cs[(rr + 0) * CPITCH + sidx];
            float v1 = Cs[(rr + 1) * CPITCH + sidx];
            float v2 = Cs[(rr + 2) * CPITCH + sidx];
            float v3 = Cs[(rr + 3) * CPITCH + sidx];
            float m = fmaxf(fmaxf(v0, v1), fmaxf(v2, v3));
            if (m > t4) {
                top5_ins(v0, t0, t1, t2, t3, t4);
                top5_ins(v1, t0, t1, t2, t3, t4);
                top5_ins(v2, t0, t1, t2, t3, t4);
                top5_ins(v3, t0, t1, t2, t3, t4);
            }
        }
        float* pp = PsC + (sidx * 4 + squad) * 5;
        pp[0] = t0; pp[1] = t1; pp[2] = t2; pp[3] = t3; pp[4] = t4;
    }
    __syncthreads();

    // ---- parallel fold: threads 0..127 fold rows, 128..255 fold cols ----
    if (tid < 128) {
        float t0 = -CUDART_INF_F, t1 = -CUDART_INF_F, t2 = -CUDART_INF_F,
              t3 = -CUDART_INF_F, t4 = -CUDART_INF_F;
        #pragma unroll
        for (int q = 0; q < 4; q++) {
            const float* pp = PsR + (tid * 4 + q) * 5;
            top5_ins(pp[0], t0, t1, t2, t3, t4);
            top5_ins(pp[1], t0, t1, t2, t3, t4);
            top5_ins(pp[2], t0, t1, t2, t3, t4);
            top5_ins(pp[3], t0, t1, t2, t3, t4);
            top5_ins(pp[4], t0, t1, t2, t3, t4);
        }
        float* gp = g_part + ((size_t)(row0 + tid) * NSLOT + J) * PSTRIDE;
        gp[0] = t0; gp[1] = t1; gp[2] = t2; gp[3] = t3; gp[4] = t4;
    } else if (tid < 256 && !DIAG) {
        float t0 = -CUDART_INF_F, t1 = -CUDART_INF_F, t2 = -CUDART_INF_F,
              t3 = -CUDART_INF_F, t4 = -CUDART_INF_F;
        #pragma unroll
        for (int q = 0; q < 4; q++) {
            const float* pp = PsC + (sidx * 4 + q) * 5;
            top5_ins(pp[0], t0, t1, t2, t3, t4);
            top5_ins(pp[1], t0, t1, t2, t3, t4);
            top5_ins(pp[2], t0, t1, t2, t3, t4);
            top5_ins(pp[3], t0, t1, t2, t3, t4);
            top5_ins(pp[4], t0, t1, t2, t3, t4);
        }
        float* gp = g_part + ((size_t)(col0 + sidx) * NSLOT + I) * PSTRIDE;
        gp[0] = t0; gp[1] = t1; gp[2] = t2; gp[3] = t3; gp[4] = t4;
    }
}

// ---------------------------------------------------------------------------
// Kernel 3: merge top-5 across 64 slots; combine with exact positive stats
// ---------------------------------------------------------------------------
__global__ void merge_kernel() {
    const int tid = threadIdx.x;
    const int lane = tid & 31;
    const int sub = lane & 7;
    const int r = blockIdx.x * 32 + (tid >> 3);

    const float4* base = (const float4*)(g_part + (size_t)r * NSLOT * PSTRIDE);
    float t0 = -CUDART_INF_F, t1 = -CUDART_INF_F, t2 = -CUDART_INF_F,
          t3 = -CUDART_INF_F, t4 = -CUDART_INF_F;
    #pragma unroll
    for (int q = 0; q < 8; q++) {
        int s = sub + q * 8;
        float4 a = base[s * 2 + 0];
        float4 d = base[s * 2 + 1];
        top5_ins(a.x, t0, t1, t2, t3, t4);
        top5_ins(a.y, t0, t1, t2, t3, t4);
        top5_ins(a.z, t0, t1, t2, t3, t4);
        top5_ins(a.w, t0, t1, t2, t3, t4);
        top5_ins(d.x, t0, t1, t2, t3, t4);
    }
    #pragma unroll
    for (int o = 1; o < 8; o <<= 1) {
        float m0 = __shfl_xor_sync(0xffffffffu, t0, o);
        float m1 = __shfl_xor_sync(0xffffffffu, t1, o);
        float m2 = __shfl_xor_sync(0xffffffffu, t2, o);
        float m3 = __shfl_xor_sync(0xffffffffu, t3, o);
        float m4 = __shfl_xor_sync(0xffffffffu, t4, o);
        top5_ins(m0, t0, t1, t2, t3, t4);
        top5_ins(m1, t0, t1, t2, t3, t4);
        top5_ins(m2, t0, t1, t2, t3, t4);
        top5_ins(m3, t0, t1, t2, t3, t4);
        top5_ins(m4, t0, t1, t2, t3, t4);
    }
    if (sub == 0) {
        float H = __expf(t0 * T_INV) + __expf(t1 * T_INV) + __expf(t2 * T_INV) +
                  __expf(t3 * T_INV) + __expf(t4 * T_INV);
        g_H[r] = (g_posn[r] > 0.f) ? H : -1.f;   // sentinel: row contributes 0
    }

    __shared__ unsigned sm[256];
    sm[tid] = fkey(t0);
    __syncthreads();
    for (int s = 128; s; s >>= 1) {
        if (tid < s) sm[tid] = max(sm[tid], sm[tid + s]);
        __syncthreads();
    }
    if (tid == 0) atomicMax(&g_Gkey, sm[0]);
}

// ---------------------------------------------------------------------------
// Kernel 4: final loss
// ---------------------------------------------------------------------------
__global__ void finalize_kernel(float* __restrict__ out) {
    __shared__ float sh[1024];
    int tid = threadIdx.x;
    float G = funkey(g_Gkey) * T_INV;
    float eG = __expf(-G);
    float sum = 0.f;
    for (int r = tid; r < BATCH; r += 1024) {
        float H = g_H[r];
        if (H >= 0.f)
            sum += __logf(g_D1[r] + eG * H) - g_B[r];
    }
    sh[tid] = sum;
    __syncthreads();
    for (int s = 512; s; s >>= 1) {
        if (tid < s) sh[tid] += sh[tid + s];
        __syncthreads();
    }
    if (tid == 0) out[0] = sh[0] / (float)BATCH;
}

// ---------------------------------------------------------------------------
extern "C" void kernel_launch(void* const* d_in, const int* in_sizes, int n_in,
                              void* d_out, int out_size) {
    const float* x   = (const float*)d_in[0];
    const int*   idx = (const int*)d_in[1];
    float*       out = (float*)d_out;

    cudaFuncSetAttribute(sim_kernel, cudaFuncAttributeMaxDynamicSharedMemorySize,
                         SMEM_BYTES);
    cudaFuncSetAttribute(gram_kernel, cudaFuncAttributeMaxDynamicSharedMemorySize,
                         GRAM_SMEM);

    prep_idx_kernel<<<1, 256>>>(idx);
    normalize_kernel<<<BATCH, 128>>>(x);
    dummy_kernel<<<1, 32>>>();      // keeps ncu's capture slot on sim_kernel
    sim_kernel<<<NTILE, THREADS, SMEM_BYTES>>>();
    // positive stats (independent of sim; ordered before merge)
    class_count_kernel<<<NCLS, 32>>>();
    class_prefix_kernel<<<1, NCLS>>>();
    class_fill_kernel<<<NCLS, 32>>>();
    gram_kernel<<<NCLS, 256, GRAM_SMEM>>>();
    merge_kernel<<<BATCH / 32, 256>>>();
    finalize_kernel<<<1, 1024>>>(out);
}